// round 7
// baseline (speedup 1.0000x reference)
#include <cuda_runtime.h>
#include <cuda_bf16.h>
#include <math.h>
#include <stdint.h>

// Problem constants
#define B_DIM     32
#define S_DIM     2048
#define ROWS      65536
#define F_DIM     8
#define D_NODE    128
#define D_K       192
#define D_OUT     64
#define N_BT      64
#define N_ET      50
#define N_EQ      100

#define OFF_BT    192
#define OFF_POP   224
#define OFF_ET    240
#define OFF_EQ    272

#define THREADS        256
#define WARPS          8
#define ROWS_PER_WARP  8
#define TILE_M         64            // rows per CTA
#define NK2            96            // 192 k-values as 96 pairs

// v layout per warp (UNCHANGED from R6): record for (k2, rp) = 16 bytes at
//   k2*80 + rp*16 : {v[2rp][2k2], v[2rp+1][2k2], v[2rp][2k2+1], v[2rp+1][2k2+1]}
#define VWARP_BYTES    (NK2 * 80)    // 7680

// W layout (NEW): Wq2[k2][q][jg] float4, q in 0..3 = (k-sub = q>>1, j-half = q&1)
//   float4 = W[2k2 + (q>>1)][8*jg + 4*(q&1) .. +3]
// One LDS.128 per (k2,q): 8 distinct contiguous 16B chunks = 128B = 1 wavefront.

// smem layout (bytes)
#define SM_W      0                                  // 96*512 = 49152
#define SM_V      49152
#define SM_CNT    (SM_V + WARPS * VWARP_BYTES)       // 110592, 64 floats
#define SMEM_BYTES (SM_CNT + 256)                    // 110848 -> 2 CTAs/SM

// Scratch (no cudaMalloc allowed)
__device__ float4 g_Wq2[NK2 * 32];
__device__ float g_btype_proj[N_BT * D_OUT];
__device__ float g_etype_proj[N_ET * D_OUT];
__device__ float g_equip_proj[N_EQ * D_OUT];
__device__ float g_pv0[D_OUT];
__device__ float g_pv1[D_OUT];

// ---------------------------------------------------------------------------
// f32x2 packed helpers (FFMA2 path — PTX-only)
// ---------------------------------------------------------------------------
__device__ __forceinline__ unsigned long long fma2(unsigned long long a,
                                                   unsigned long long b,
                                                   unsigned long long c) {
    unsigned long long d;
    asm("fma.rn.f32x2 %0, %1, %2, %3;" : "=l"(d) : "l"(a), "l"(b), "l"(c));
    return d;
}
__device__ __forceinline__ unsigned long long bcast2(float x) {
    unsigned long long d;
    unsigned int xi = __float_as_uint(x);
    asm("mov.b64 %0, {%1, %1};" : "=l"(d) : "r"(xi));
    return d;
}
__device__ __forceinline__ void unpack2(unsigned long long v, float& lo, float& hi) {
    unsigned int a, b;
    asm("mov.b64 {%0, %1}, %2;" : "=r"(a), "=r"(b) : "l"(v));
    lo = __uint_as_float(a);
    hi = __uint_as_float(b);
}

// ---------------------------------------------------------------------------
// Precompute: project small-vocab tables + pack Wq2
// ---------------------------------------------------------------------------
__global__ void precompute_tables(const float* __restrict__ btype_table,
                                  const float* __restrict__ etype_table,
                                  const float* __restrict__ equip_table,
                                  const float* __restrict__ pop_w,
                                  const float* __restrict__ pop_b,
                                  const float* __restrict__ proj_w,
                                  const float* __restrict__ proj_b) {
    int j = threadIdx.x;
    int n = blockIdx.x;
    if (n < N_BT) {
        float a = 0.f;
        #pragma unroll
        for (int d = 0; d < 32; ++d)
            a += btype_table[n * 32 + d] * proj_w[(OFF_BT + d) * D_OUT + j];
        g_btype_proj[n * D_OUT + j] = a;
    } else if (n < N_BT + N_ET) {
        int m = n - N_BT;
        float a = 0.f;
        #pragma unroll
        for (int d = 0; d < 32; ++d)
            a += etype_table[m * 32 + d] * proj_w[(OFF_ET + d) * D_OUT + j];
        g_etype_proj[m * D_OUT + j] = a;
    } else if (n < N_BT + N_ET + N_EQ) {
        int m = n - N_BT - N_ET;
        float a = 0.f;
        #pragma unroll
        for (int d = 0; d < 32; ++d)
            a += equip_table[m * 32 + d] * proj_w[(OFF_EQ + d) * D_OUT + j];
        g_equip_proj[m * D_OUT + j] = a;
    } else if (n == N_BT + N_ET + N_EQ) {
        float a0 = 0.f, a1 = 0.f;
        #pragma unroll
        for (int d = 0; d < 16; ++d) {
            float w = proj_w[(OFF_POP + d) * D_OUT + j];
            a0 += pop_w[d] * w;
            a1 += pop_b[d] * w;
        }
        g_pv0[j] = a0;
        g_pv1[j] = a1 + proj_b[j];
    } else {
        int k2 = n - (N_BT + N_ET + N_EQ + 1);     // 0..95
        if (j < 32) {
            int q  = j >> 3;          // 0..3
            int jg = j & 7;           // 0..7
            const float* src = proj_w + (2 * k2 + (q >> 1)) * D_OUT
                                      + 8 * jg + 4 * (q & 1);
            g_Wq2[k2 * 32 + q * 8 + jg] =
                make_float4(src[0], src[1], src[2], src[3]);
        }
    }
}

// ---------------------------------------------------------------------------
// Main kernel: 256 threads / 8 warps, 8 rows per warp, 2 CTAs/SM.
// Lane tile: rg = lane&3 -> row pair (2rg, 2rg+1); jg = lane>>2 -> j 8jg..8jg+7.
// ---------------------------------------------------------------------------
__global__ void __launch_bounds__(THREADS, 2)
combined_embedding_kernel(const int*   __restrict__ nbr_ids,
                          const float* __restrict__ time_feat,
                          const int*   __restrict__ bt_ids,
                          const float* __restrict__ counts,
                          const float* __restrict__ population,
                          const int*   __restrict__ et_ids,
                          const int*   __restrict__ eq_ids,
                          const float* __restrict__ node2vec,
                          const float* __restrict__ t2v_w,
                          const float* __restrict__ t2v_b,
                          float*       __restrict__ out) {
    extern __shared__ char smem[];
    float4* Wsm      = (float4*)(smem + SM_W);
    float*  counts_s = (float*)(smem + SM_CNT);

    const int tid  = threadIdx.x;
    const int lane = tid & 31;
    const int warp = tid >> 5;
    const int ctabase = blockIdx.x * TILE_M;
    const int rowbase = ctabase + warp * ROWS_PER_WARP;

    // --- stage packed W (12 float4 per thread) ---
    #pragma unroll
    for (int i = 0; i < 12; ++i)
        Wsm[i * THREADS + tid] = g_Wq2[i * THREADS + tid];

    // --- counts_sum for this CTA's 64 s-values (4 threads per s) ---
    {
        int sl = tid >> 2, q = tid & 3;
        int sg = (ctabase & (S_DIM - 1)) + sl;
        float p = 0.f;
        #pragma unroll
        for (int i = 0; i < 8; ++i) p += counts[(q * 8 + i) * S_DIM + sg];
        p += __shfl_xor_sync(0xffffffffu, p, 1);
        p += __shfl_xor_sync(0xffffffffu, p, 2);
        if (q == 0) counts_s[sl] = p;
    }
    __syncthreads();

    char* vw = smem + SM_V + warp * VWARP_BYTES;

    // per-lane t2v constants: lane produces t2v elems kk=lane and kk=32+lane
    const float tw1 = t2v_w[lane],      tb1 = t2v_b[lane];
    const float tw2 = t2v_w[32 + lane], tb2 = t2v_b[32 + lane];
    const int  f1 = lane >> 3;
    const bool do_sin = (lane & 7) != 0;

    int nid[ROWS_PER_WARP];
    #pragma unroll
    for (int r = 0; r < ROWS_PER_WARP; ++r) nid[r] = nbr_ids[rowbase + r];

    // --- Phase 1 (unchanged from R6): build v buffer ---
    #pragma unroll
    for (int rp = 0; rp < 4; ++rp) {
        int row0 = rowbase + 2 * rp;
        int row1 = row0 + 1;

        float4 e = ((const float4*)(node2vec + (size_t)nid[2 * rp]     * D_NODE))[lane];
        float4 o = ((const float4*)(node2vec + (size_t)nid[2 * rp + 1] * D_NODE))[lane];
        char* p0 = vw + lane * 160 + rp * 16;
        *(float4*)p0        = make_float4(e.x, o.x, e.y, o.y);
        *(float4*)(p0 + 80) = make_float4(e.z, o.z, e.w, o.w);

        float x10 = time_feat[row0 * F_DIM + f1];
        float x11 = time_feat[row1 * F_DIM + f1];
        float x20 = time_feat[row0 * F_DIM + 4 + f1];
        float x21 = time_feat[row1 * F_DIM + 4 + f1];
        float ae1 = fmaf(x10, tw1, tb1), ao1 = fmaf(x11, tw1, tb1);
        float ae2 = fmaf(x20, tw2, tb2), ao2 = fmaf(x21, tw2, tb2);
        float e1 = do_sin ? __sinf(ae1) : ae1;
        float o1 = do_sin ? __sinf(ao1) : ao1;
        float e2 = do_sin ? __sinf(ae2) : ae2;
        float o2 = do_sin ? __sinf(ao2) : ao2;
        int soff = rp * 16 + ((lane & 1) << 3);
        *(float2*)(vw + (64 + (lane >> 1)) * 80 + soff) = make_float2(e1, o1);
        *(float2*)(vw + (80 + (lane >> 1)) * 80 + soff) = make_float2(e2, o2);
    }
    __syncwarp();

    // --- Phase 2: register-tiled matvec, lane = 2 rows x 8 j ---
    const int rg = lane & 3;
    const int jg = lane >> 2;

    // acc[r][p] = packed outputs (j=8jg+2p, j=8jg+2p+1) for row (2rg + r)
    unsigned long long acc[2][4];
    #pragma unroll
    for (int r = 0; r < 2; ++r)
        #pragma unroll
        for (int p = 0; p < 4; ++p) acc[r][p] = 0ull;

    const char* Wl = (const char*)Wsm + jg * 16;
    const char* vl = vw + rg * 16;

    #pragma unroll 4
    for (int k2 = 0; k2 < NK2; ++k2) {
        float4 vv = *(const float4*)(vl + k2 * 80);
        unsigned long long b00 = bcast2(vv.x);   // row0 @ k0
        unsigned long long b10 = bcast2(vv.y);   // row1 @ k0
        unsigned long long b01 = bcast2(vv.z);   // row0 @ k1
        unsigned long long b11 = bcast2(vv.w);   // row1 @ k1

        const char* wb = Wl + k2 * 512;
        ulonglong2 w00 = *(const ulonglong2*)(wb);         // k0, jp 0,1
        ulonglong2 w01 = *(const ulonglong2*)(wb + 128);   // k0, jp 2,3
        ulonglong2 w10 = *(const ulonglong2*)(wb + 256);   // k1, jp 0,1
        ulonglong2 w11 = *(const ulonglong2*)(wb + 384);   // k1, jp 2,3

        acc[0][0] = fma2(b00, w00.x, acc[0][0]);
        acc[0][1] = fma2(b00, w00.y, acc[0][1]);
        acc[0][2] = fma2(b00, w01.x, acc[0][2]);
        acc[0][3] = fma2(b00, w01.y, acc[0][3]);
        acc[1][0] = fma2(b10, w00.x, acc[1][0]);
        acc[1][1] = fma2(b10, w00.y, acc[1][1]);
        acc[1][2] = fma2(b10, w01.x, acc[1][2]);
        acc[1][3] = fma2(b10, w01.y, acc[1][3]);
        acc[0][0] = fma2(b01, w10.x, acc[0][0]);
        acc[0][1] = fma2(b01, w10.y, acc[0][1]);
        acc[0][2] = fma2(b01, w11.x, acc[0][2]);
        acc[0][3] = fma2(b01, w11.y, acc[0][3]);
        acc[1][0] = fma2(b11, w10.x, acc[1][0]);
        acc[1][1] = fma2(b11, w10.y, acc[1][1]);
        acc[1][2] = fma2(b11, w11.x, acc[1][2]);
        acc[1][3] = fma2(b11, w11.y, acc[1][3]);
    }

    // --- Epilogue: lane owns rows (2rg, 2rg+1), j = 8jg..8jg+7 ---
    #pragma unroll
    for (int r = 0; r < 2; ++r) {
        int rl  = warp * ROWS_PER_WARP + 2 * rg + r;
        int row = ctabase + rl;
        float res[8];
        #pragma unroll
        for (int p = 0; p < 4; ++p)
            unpack2(acc[r][p], res[2 * p], res[2 * p + 1]);

        float c = counts_s[rl];
        float pp = population[row];
        int bt = bt_ids[row], et = et_ids[row], eq = eq_ids[row];

        const float* tb = g_btype_proj + bt * D_OUT + 8 * jg;
        const float* te = g_etype_proj + et * D_OUT + 8 * jg;
        const float* tq = g_equip_proj + eq * D_OUT + 8 * jg;
        const float* v0 = g_pv0 + 8 * jg;
        const float* v1 = g_pv1 + 8 * jg;

        float4 tb0 = *(const float4*)tb,       tb1 = *(const float4*)(tb + 4);
        float4 te0 = *(const float4*)te,       te1 = *(const float4*)(te + 4);
        float4 tq0 = *(const float4*)tq,       tq1 = *(const float4*)(tq + 4);
        float4 pv00 = *(const float4*)v0,      pv01 = *(const float4*)(v0 + 4);
        float4 pv10 = *(const float4*)v1,      pv11 = *(const float4*)(v1 + 4);

        res[0] += c * tb0.x + te0.x + tq0.x + pp * pv00.x + pv10.x;
        res[1] += c * tb0.y + te0.y + tq0.y + pp * pv00.y + pv10.y;
        res[2] += c * tb0.z + te0.z + tq0.z + pp * pv00.z + pv10.z;
        res[3] += c * tb0.w + te0.w + tq0.w + pp * pv00.w + pv10.w;
        res[4] += c * tb1.x + te1.x + tq1.x + pp * pv01.x + pv11.x;
        res[5] += c * tb1.y + te1.y + tq1.y + pp * pv01.y + pv11.y;
        res[6] += c * tb1.z + te1.z + tq1.z + pp * pv01.z + pv11.z;
        res[7] += c * tb1.w + te1.w + tq1.w + pp * pv01.w + pv11.w;

        float* op = out + (size_t)row * D_OUT + 8 * jg;
        *(float4*)op       = make_float4(res[0], res[1], res[2], res[3]);
        *(float4*)(op + 4) = make_float4(res[4], res[5], res[6], res[7]);
    }
}

// ---------------------------------------------------------------------------
extern "C" void kernel_launch(void* const* d_in, const int* in_sizes, int n_in,
                              void* d_out, int out_size) {
    const int*   nbr     = (const int*)  d_in[0];
    const float* tfeat   = (const float*)d_in[1];
    const int*   bt      = (const int*)  d_in[2];
    const float* counts  = (const float*)d_in[3];
    const float* pop     = (const float*)d_in[4];
    const int*   et      = (const int*)  d_in[5];
    const int*   eq      = (const int*)  d_in[6];
    const float* n2v     = (const float*)d_in[7];
    const float* t2vw    = (const float*)d_in[8];
    const float* t2vb    = (const float*)d_in[9];
    const float* btt     = (const float*)d_in[10];
    const float* popw    = (const float*)d_in[11];
    const float* popb    = (const float*)d_in[12];
    const float* ett     = (const float*)d_in[13];
    const float* eqt     = (const float*)d_in[14];
    const float* pw      = (const float*)d_in[15];
    const float* pb      = (const float*)d_in[16];
    float*       out     = (float*)d_out;

    precompute_tables<<<N_BT + N_ET + N_EQ + 1 + NK2, 64>>>(
        btt, ett, eqt, popw, popb, pw, pb);

    cudaFuncSetAttribute(combined_embedding_kernel,
                         cudaFuncAttributeMaxDynamicSharedMemorySize, SMEM_BYTES);
    combined_embedding_kernel<<<ROWS / TILE_M, THREADS, SMEM_BYTES>>>(
        nbr, tfeat, bt, counts, pop, et, eq, n2v, t2vw, t2vb, out);
}

// round 8
// speedup vs baseline: 1.1414x; 1.1414x over previous
#include <cuda_runtime.h>
#include <cuda_bf16.h>
#include <math.h>
#include <stdint.h>

// Problem constants
#define B_DIM     32
#define S_DIM     2048
#define ROWS      65536
#define F_DIM     8
#define D_NODE    128
#define D_K       192
#define D_OUT     64
#define N_BT      64
#define N_ET      50
#define N_EQ      100

#define OFF_BT    192
#define OFF_POP   224
#define OFF_ET    240
#define OFF_EQ    272

#define THREADS        256
#define WARPS          8
#define ROWS_PER_WARP  8
#define TILE_M         64
#define NK2            96

// v layout per warp (UNCHANGED from R6 — proven): record (k2, rp) = 16B at
//   k2*80 + rp*16 : {v[2rp][2k2], v[2rp+1][2k2], v[2rp][2k2+1], v[2rp+1][2k2+1]}
// Phase-2 lane kb reads its 8B half: (v[2rp][2k2+kb], v[2rp+1][2k2+kb]).
#define VWARP_BYTES    (NK2 * 80)    // 7680

// W layout (NEW, k-major): float at k2*512 + kb*256 + j*4.
// Lane (kb,jq) reads float4 at k2*512 + lane*16 -> all 4 phases distinct 128B.

// smem layout (bytes)
#define SM_W      0                                  // 96*512 = 49152
#define SM_V      49152
#define SM_CNT    (SM_V + WARPS * VWARP_BYTES)       // 110592
#define SMEM_BYTES (SM_CNT + 256)                    // 110848 -> 2 CTAs/SM

// Scratch (no cudaMalloc allowed)
__device__ float4 g_W3[NK2 * 32];
__device__ float g_btype_proj[N_BT * D_OUT];
__device__ float g_etype_proj[N_ET * D_OUT];
__device__ float g_equip_proj[N_EQ * D_OUT];
__device__ float g_pv0[D_OUT];
__device__ float g_pv1[D_OUT];

// ---------------------------------------------------------------------------
// f32x2 packed helpers (PTX-only)
// ---------------------------------------------------------------------------
__device__ __forceinline__ unsigned long long fma2(unsigned long long a,
                                                   unsigned long long b,
                                                   unsigned long long c) {
    unsigned long long d;
    asm("fma.rn.f32x2 %0, %1, %2, %3;" : "=l"(d) : "l"(a), "l"(b), "l"(c));
    return d;
}
__device__ __forceinline__ unsigned long long add2(unsigned long long a,
                                                   unsigned long long b) {
    unsigned long long d;
    asm("add.rn.f32x2 %0, %1, %2;" : "=l"(d) : "l"(a), "l"(b));
    return d;
}
__device__ __forceinline__ unsigned long long bcast2(float x) {
    unsigned long long d;
    unsigned int xi = __float_as_uint(x);
    asm("mov.b64 %0, {%1, %1};" : "=l"(d) : "r"(xi));
    return d;
}
__device__ __forceinline__ void unpack2(unsigned long long v, float& lo, float& hi) {
    unsigned int a, b;
    asm("mov.b64 {%0, %1}, %2;" : "=r"(a), "=r"(b) : "l"(v));
    lo = __uint_as_float(a);
    hi = __uint_as_float(b);
}
__device__ __forceinline__ unsigned long long shfl_xor64(unsigned long long v, int m) {
    unsigned int lo = (unsigned int)v, hi = (unsigned int)(v >> 32);
    lo = __shfl_xor_sync(0xffffffffu, lo, m);
    hi = __shfl_xor_sync(0xffffffffu, hi, m);
    return ((unsigned long long)hi << 32) | lo;
}

// ---------------------------------------------------------------------------
// Precompute: project small-vocab tables + pack W (k-major)
// ---------------------------------------------------------------------------
__global__ void precompute_tables(const float* __restrict__ btype_table,
                                  const float* __restrict__ etype_table,
                                  const float* __restrict__ equip_table,
                                  const float* __restrict__ pop_w,
                                  const float* __restrict__ pop_b,
                                  const float* __restrict__ proj_w,
                                  const float* __restrict__ proj_b) {
    int j = threadIdx.x;
    int n = blockIdx.x;
    if (n < N_BT) {
        float a = 0.f;
        #pragma unroll
        for (int d = 0; d < 32; ++d)
            a += btype_table[n * 32 + d] * proj_w[(OFF_BT + d) * D_OUT + j];
        g_btype_proj[n * D_OUT + j] = a;
    } else if (n < N_BT + N_ET) {
        int m = n - N_BT;
        float a = 0.f;
        #pragma unroll
        for (int d = 0; d < 32; ++d)
            a += etype_table[m * 32 + d] * proj_w[(OFF_ET + d) * D_OUT + j];
        g_etype_proj[m * D_OUT + j] = a;
    } else if (n < N_BT + N_ET + N_EQ) {
        int m = n - N_BT - N_ET;
        float a = 0.f;
        #pragma unroll
        for (int d = 0; d < 32; ++d)
            a += equip_table[m * 32 + d] * proj_w[(OFF_EQ + d) * D_OUT + j];
        g_equip_proj[m * D_OUT + j] = a;
    } else if (n == N_BT + N_ET + N_EQ) {
        float a0 = 0.f, a1 = 0.f;
        #pragma unroll
        for (int d = 0; d < 16; ++d) {
            float w = proj_w[(OFF_POP + d) * D_OUT + j];
            a0 += pop_w[d] * w;
            a1 += pop_b[d] * w;
        }
        g_pv0[j] = a0;
        g_pv1[j] = a1 + proj_b[j];
    } else {
        int k2 = n - (N_BT + N_ET + N_EQ + 1);     // 0..95
        if (j < 32) {
            int kb = j >> 4;          // 0,1
            int jq = j & 15;          // 0..15
            const float* src = proj_w + (2 * k2 + kb) * D_OUT + 4 * jq;
            g_W3[k2 * 32 + j] = make_float4(src[0], src[1], src[2], src[3]);
        }
    }
}

// ---------------------------------------------------------------------------
// Main kernel: 256 threads / 8 warps, 8 rows/warp, 2 CTAs/SM.
// Phase-2 lane tile: kb = lane>>4 (k parity), jq = lane&15 (j-quad 4jq..4jq+3).
// ---------------------------------------------------------------------------
__global__ void __launch_bounds__(THREADS, 2)
combined_embedding_kernel(const int*   __restrict__ nbr_ids,
                          const float* __restrict__ time_feat,
                          const int*   __restrict__ bt_ids,
                          const float* __restrict__ counts,
                          const float* __restrict__ population,
                          const int*   __restrict__ et_ids,
                          const int*   __restrict__ eq_ids,
                          const float* __restrict__ node2vec,
                          const float* __restrict__ t2v_w,
                          const float* __restrict__ t2v_b,
                          float*       __restrict__ out) {
    extern __shared__ char smem[];
    float4* Wsm      = (float4*)(smem + SM_W);
    float*  counts_s = (float*)(smem + SM_CNT);

    const int tid  = threadIdx.x;
    const int lane = tid & 31;
    const int warp = tid >> 5;
    const int ctabase = blockIdx.x * TILE_M;
    const int rowbase = ctabase + warp * ROWS_PER_WARP;

    // --- stage packed W (12 float4 per thread) ---
    #pragma unroll
    for (int i = 0; i < 12; ++i)
        Wsm[i * THREADS + tid] = g_W3[i * THREADS + tid];

    // --- counts_sum for this CTA's 64 s-values ---
    {
        int sl = tid >> 2, q = tid & 3;
        int sg = (ctabase & (S_DIM - 1)) + sl;
        float p = 0.f;
        #pragma unroll
        for (int i = 0; i < 8; ++i) p += counts[(q * 8 + i) * S_DIM + sg];
        p += __shfl_xor_sync(0xffffffffu, p, 1);
        p += __shfl_xor_sync(0xffffffffu, p, 2);
        if (q == 0) counts_s[sl] = p;
    }
    __syncthreads();

    char* vw = smem + SM_V + warp * VWARP_BYTES;

    // per-lane t2v constants (phase 1, unchanged from R6)
    const float tw1 = t2v_w[lane],      tb1 = t2v_b[lane];
    const float tw2 = t2v_w[32 + lane], tb2 = t2v_b[32 + lane];
    const int  f1 = lane >> 3;
    const bool do_sin = (lane & 7) != 0;

    int nid[ROWS_PER_WARP];
    #pragma unroll
    for (int r = 0; r < ROWS_PER_WARP; ++r) nid[r] = nbr_ids[rowbase + r];

    // --- Phase 1 (verbatim R6): build v buffer ---
    #pragma unroll
    for (int rp = 0; rp < 4; ++rp) {
        int row0 = rowbase + 2 * rp;
        int row1 = row0 + 1;

        float4 e = ((const float4*)(node2vec + (size_t)nid[2 * rp]     * D_NODE))[lane];
        float4 o = ((const float4*)(node2vec + (size_t)nid[2 * rp + 1] * D_NODE))[lane];
        char* p0 = vw + lane * 160 + rp * 16;
        *(float4*)p0        = make_float4(e.x, o.x, e.y, o.y);
        *(float4*)(p0 + 80) = make_float4(e.z, o.z, e.w, o.w);

        float x10 = time_feat[row0 * F_DIM + f1];
        float x11 = time_feat[row1 * F_DIM + f1];
        float x20 = time_feat[row0 * F_DIM + 4 + f1];
        float x21 = time_feat[row1 * F_DIM + 4 + f1];
        float ae1 = fmaf(x10, tw1, tb1), ao1 = fmaf(x11, tw1, tb1);
        float ae2 = fmaf(x20, tw2, tb2), ao2 = fmaf(x21, tw2, tb2);
        float e1 = do_sin ? __sinf(ae1) : ae1;
        float o1 = do_sin ? __sinf(ao1) : ao1;
        float e2 = do_sin ? __sinf(ae2) : ae2;
        float o2 = do_sin ? __sinf(ao2) : ao2;
        int soff = rp * 16 + ((lane & 1) << 3);
        *(float2*)(vw + (64 + (lane >> 1)) * 80 + soff) = make_float2(e1, o1);
        *(float2*)(vw + (80 + (lane >> 1)) * 80 + soff) = make_float2(e2, o2);
    }
    __syncwarp();

    // --- Phase 2: lane (kb, jq); k-parity split, shuffle-reduced at the end ---
    const int kb = lane >> 4;
    const int jq = lane & 15;

    // acc[rp][js] packs (out[2rp][4jq+js], out[2rp+1][4jq+js]), partial over k%2==kb
    unsigned long long acc[4][4];
    #pragma unroll
    for (int rp = 0; rp < 4; ++rp)
        #pragma unroll
        for (int js = 0; js < 4; ++js) acc[rp][js] = 0ull;

    const char* Wl = (const char*)Wsm + lane * 16;
    const char* vl = vw + kb * 8;

    #pragma unroll 4
    for (int k2 = 0; k2 < NK2; ++k2) {
        float4 w = *(const float4*)(Wl + k2 * 512);   // W[2k2+kb][4jq..4jq+3]
        unsigned long long w0 = bcast2(w.x);
        unsigned long long w1 = bcast2(w.y);
        unsigned long long w2 = bcast2(w.z);
        unsigned long long w3 = bcast2(w.w);
        const char* vb = vl + k2 * 80;
        #pragma unroll
        for (int rp = 0; rp < 4; ++rp) {
            unsigned long long vp = *(const unsigned long long*)(vb + rp * 16);
            acc[rp][0] = fma2(vp, w0, acc[rp][0]);
            acc[rp][1] = fma2(vp, w1, acc[rp][1]);
            acc[rp][2] = fma2(vp, w2, acc[rp][2]);
            acc[rp][3] = fma2(vp, w3, acc[rp][3]);
        }
    }

    // merge k-parity halves: lane L <-> L^16 hold the two halves of the same tile
    #pragma unroll
    for (int rp = 0; rp < 4; ++rp)
        #pragma unroll
        for (int js = 0; js < 4; ++js)
            acc[rp][js] = add2(acc[rp][js], shfl_xor64(acc[rp][js], 16));

    // --- Epilogue: lane owns rows 4kb..4kb+3 (local), j = 4jq..4jq+3 ---
    #pragma unroll
    for (int rr = 0; rr < 4; ++rr) {
        int rl  = warp * ROWS_PER_WARP + 4 * kb + rr;
        int row = ctabase + rl;
        int rp  = 2 * kb + (rr >> 1);
        int h   = rr & 1;

        float res[4];
        #pragma unroll
        for (int js = 0; js < 4; ++js) {
            float lo, hi;
            unpack2(acc[rp][js], lo, hi);
            res[js] = h ? hi : lo;
        }

        float c  = counts_s[rl];
        float pp = population[row];
        int bt = bt_ids[row], et = et_ids[row], eq = eq_ids[row];

        float4 tb = *(const float4*)(g_btype_proj + bt * D_OUT + 4 * jq);
        float4 te = *(const float4*)(g_etype_proj + et * D_OUT + 4 * jq);
        float4 tq = *(const float4*)(g_equip_proj + eq * D_OUT + 4 * jq);
        float4 v0 = *(const float4*)(g_pv0 + 4 * jq);
        float4 v1 = *(const float4*)(g_pv1 + 4 * jq);

        res[0] += c * tb.x + te.x + tq.x + pp * v0.x + v1.x;
        res[1] += c * tb.y + te.y + tq.y + pp * v0.y + v1.y;
        res[2] += c * tb.z + te.z + tq.z + pp * v0.z + v1.z;
        res[3] += c * tb.w + te.w + tq.w + pp * v0.w + v1.w;

        *(float4*)(out + (size_t)row * D_OUT + 4 * jq) =
            make_float4(res[0], res[1], res[2], res[3]);
    }
}

// ---------------------------------------------------------------------------
extern "C" void kernel_launch(void* const* d_in, const int* in_sizes, int n_in,
                              void* d_out, int out_size) {
    const int*   nbr     = (const int*)  d_in[0];
    const float* tfeat   = (const float*)d_in[1];
    const int*   bt      = (const int*)  d_in[2];
    const float* counts  = (const float*)d_in[3];
    const float* pop     = (const float*)d_in[4];
    const int*   et      = (const int*)  d_in[5];
    const int*   eq      = (const int*)  d_in[6];
    const float* n2v     = (const float*)d_in[7];
    const float* t2vw    = (const float*)d_in[8];
    const float* t2vb    = (const float*)d_in[9];
    const float* btt     = (const float*)d_in[10];
    const float* popw    = (const float*)d_in[11];
    const float* popb    = (const float*)d_in[12];
    const float* ett     = (const float*)d_in[13];
    const float* eqt     = (const float*)d_in[14];
    const float* pw      = (const float*)d_in[15];
    const float* pb      = (const float*)d_in[16];
    float*       out     = (float*)d_out;

    precompute_tables<<<N_BT + N_ET + N_EQ + 1 + NK2, 64>>>(
        btt, ett, eqt, popw, popb, pw, pb);

    cudaFuncSetAttribute(combined_embedding_kernel,
                         cudaFuncAttributeMaxDynamicSharedMemorySize, SMEM_BYTES);
    combined_embedding_kernel<<<ROWS / TILE_M, THREADS, SMEM_BYTES>>>(
        nbr, tfeat, bt, counts, pop, et, eq, n2v, t2vw, t2vb, out);
}

// round 9
// speedup vs baseline: 1.4274x; 1.2506x over previous
#include <cuda_runtime.h>
#include <cuda_bf16.h>
#include <math.h>
#include <stdint.h>

// Problem constants
#define B_DIM     32
#define S_DIM     2048
#define ROWS      65536
#define F_DIM     8
#define D_NODE    128
#define D_K       192
#define D_OUT     64
#define N_BT      64
#define N_ET      50
#define N_EQ      100

#define OFF_BT    192
#define OFF_POP   224
#define OFF_ET    240
#define OFF_EQ    272

#define THREADS   256
#define TILE_M    64
#define NKS       12                  // 192 / 16 k per mma step

// bf16 row stride: 192 data + 8 pad = 200 elems = 400 B (16B-aligned, and
// 400/4=100 ≡ 4 (mod 32) banks -> ldmatrix 8-row phases conflict-free)
#define WSTRIDE   200
#define WBYTES    (64 * WSTRIDE * 2)  // 25600 per precision

// smem layout (bytes)
#define SM_W_HI   0
#define SM_W_LO   25600
#define SM_A_HI   51200
#define SM_A_LO   76800
#define SM_CNT    102400
#define SMEM_BYTES 102656
#define SM_DT     SM_A_HI             // Dt[64][72] f32 = 18432 B, reuse A_hi
#define DT_STRIDE 72

// Scratch (no cudaMalloc allowed)
__device__ uint4 g_Wbf[2 * 1600];     // Wt hi then lo, [64][200] bf16 each
__device__ float g_btype_proj[N_BT * D_OUT];
__device__ float g_etype_proj[N_ET * D_OUT];
__device__ float g_equip_proj[N_EQ * D_OUT];
__device__ float g_pv0[D_OUT];
__device__ float g_pv1[D_OUT];

// ---------------------------------------------------------------------------
// helpers
// ---------------------------------------------------------------------------
__device__ __forceinline__ uint32_t smem_u32(const void* p) {
    uint32_t a;
    asm("{ .reg .u64 t; cvta.to.shared.u64 t, %1; cvt.u32.u64 %0, t; }"
        : "=r"(a) : "l"(p));
    return a;
}
// pack the TRUNCATED-bf16 high halves of two floats: low16 = hi(x0), high16 = hi(x1)
__device__ __forceinline__ uint32_t prmt_hi(float x0, float x1) {
    uint32_t d;
    asm("prmt.b32 %0, %1, %2, 0x7632;"
        : "=r"(d) : "r"(__float_as_uint(x0)), "r"(__float_as_uint(x1)));
    return d;
}
__device__ __forceinline__ float trunc_bf16(float x) {
    return __uint_as_float(__float_as_uint(x) & 0xFFFF0000u);
}
// pack rn-bf16 of two floats: low16 = bf16(x0), high16 = bf16(x1)
__device__ __forceinline__ uint32_t pack_bf16(float x0, float x1) {
    uint32_t d;
    asm("cvt.rn.bf16x2.f32 %0, %1, %2;" : "=r"(d) : "f"(x1), "f"(x0));
    return d;
}
__device__ __forceinline__ void ldsm_x4(uint32_t addr, uint32_t* r) {
    asm volatile("ldmatrix.sync.aligned.m8n8.x4.shared.b16 {%0,%1,%2,%3}, [%4];"
                 : "=r"(r[0]), "=r"(r[1]), "=r"(r[2]), "=r"(r[3]) : "r"(addr));
}
__device__ __forceinline__ void mma_bf16(float* d, const uint32_t* a,
                                         uint32_t b0, uint32_t b1) {
    asm volatile(
        "mma.sync.aligned.m16n8k16.row.col.f32.bf16.bf16.f32 "
        "{%0,%1,%2,%3}, {%4,%5,%6,%7}, {%8,%9}, {%0,%1,%2,%3};"
        : "+f"(d[0]), "+f"(d[1]), "+f"(d[2]), "+f"(d[3])
        : "r"(a[0]), "r"(a[1]), "r"(a[2]), "r"(a[3]), "r"(b0), "r"(b1));
}

// ---------------------------------------------------------------------------
// Precompute: project small-vocab tables + pack Wt (bf16 hi/lo, n-major)
// grid = 215 + 64 blocks of 64 threads
// ---------------------------------------------------------------------------
__global__ void precompute_tables(const float* __restrict__ btype_table,
                                  const float* __restrict__ etype_table,
                                  const float* __restrict__ equip_table,
                                  const float* __restrict__ pop_w,
                                  const float* __restrict__ pop_b,
                                  const float* __restrict__ proj_w,
                                  const float* __restrict__ proj_b) {
    int j = threadIdx.x;
    int n = blockIdx.x;
    if (n < N_BT) {
        float a = 0.f;
        #pragma unroll
        for (int d = 0; d < 32; ++d)
            a += btype_table[n * 32 + d] * proj_w[(OFF_BT + d) * D_OUT + j];
        g_btype_proj[n * D_OUT + j] = a;
    } else if (n < N_BT + N_ET) {
        int m = n - N_BT;
        float a = 0.f;
        #pragma unroll
        for (int d = 0; d < 32; ++d)
            a += etype_table[m * 32 + d] * proj_w[(OFF_ET + d) * D_OUT + j];
        g_etype_proj[m * D_OUT + j] = a;
    } else if (n < N_BT + N_ET + N_EQ) {
        int m = n - N_BT - N_ET;
        float a = 0.f;
        #pragma unroll
        for (int d = 0; d < 32; ++d)
            a += equip_table[m * 32 + d] * proj_w[(OFF_EQ + d) * D_OUT + j];
        g_equip_proj[m * D_OUT + j] = a;
    } else if (n == N_BT + N_ET + N_EQ) {
        float a0 = 0.f, a1 = 0.f;
        #pragma unroll
        for (int d = 0; d < 16; ++d) {
            float w = proj_w[(OFF_POP + d) * D_OUT + j];
            a0 += pop_w[d] * w;
            a1 += pop_b[d] * w;
        }
        g_pv0[j] = a0;
        g_pv1[j] = a1 + proj_b[j];
    } else {
        int nc = n - (N_BT + N_ET + N_EQ + 1);   // output col 0..63
        unsigned short* hi = (unsigned short*)g_Wbf;
        unsigned short* lo = hi + 64 * WSTRIDE;
        #pragma unroll
        for (int i = 0; i < 3; ++i) {
            int k = j + 64 * i;
            float x  = proj_w[k * D_OUT + nc];
            float xh = trunc_bf16(x);
            hi[nc * WSTRIDE + k] = (unsigned short)(__float_as_uint(x) >> 16);
            lo[nc * WSTRIDE + k] =
                __bfloat16_as_ushort(__float2bfloat16(x - xh));
        }
    }
}

// ---------------------------------------------------------------------------
// Main kernel: TILE 64 rows, 256 threads / 8 warps, 2 CTAs/SM.
// Warp w: m-tile mt = w>>1 (16 rows), n-half nh = w&1 (32 cols).
// Split-bf16 3-pass mma.sync GEMM; Dt smem transpose; R8 epilogue.
// ---------------------------------------------------------------------------
__global__ void __launch_bounds__(THREADS, 2)
combined_embedding_kernel(const int*   __restrict__ nbr_ids,
                          const float* __restrict__ time_feat,
                          const int*   __restrict__ bt_ids,
                          const float* __restrict__ counts,
                          const float* __restrict__ population,
                          const int*   __restrict__ et_ids,
                          const int*   __restrict__ eq_ids,
                          const float* __restrict__ node2vec,
                          const float* __restrict__ t2v_w,
                          const float* __restrict__ t2v_b,
                          float*       __restrict__ out) {
    extern __shared__ char smem[];
    const uint32_t sb = smem_u32(smem);
    float* counts_s = (float*)(smem + SM_CNT);

    const int tid  = threadIdx.x;
    const int lane = tid & 31;
    const int warp = tid >> 5;
    const int ctabase = blockIdx.x * TILE_M;

    // --- stage Wt hi/lo (plain copy; global layout mirrors smem) ---
    {
        uint4* dst = (uint4*)smem;               // SM_W_HI..SM_W_LO contiguous
        #pragma unroll
        for (int i = 0; i < 13; ++i) {
            int idx = i * THREADS + tid;
            if (idx < 3200) dst[idx] = g_Wbf[idx];
        }
    }

    // --- counts_sum for this CTA's 64 s-values ---
    {
        int sl = tid >> 2, q = tid & 3;
        int sg = (ctabase & (S_DIM - 1)) + sl;
        float p = 0.f;
        #pragma unroll
        for (int i = 0; i < 8; ++i) p += counts[(q * 8 + i) * S_DIM + sg];
        p += __shfl_xor_sync(0xffffffffu, p, 1);
        p += __shfl_xor_sync(0xffffffffu, p, 2);
        if (q == 0) counts_s[sl] = p;
    }

    // --- Phase 1: stage A (hi/lo bf16, row-major stride 400B) ---
    {
        int rt = tid >> 2, q = tid & 3;          // row 0..63, k-quarter
        int row = ctabase + rt;
        int nid = nbr_ids[row];
        const float4* src = (const float4*)(node2vec + (size_t)nid * D_NODE) + q * 8;
        char* ah = smem + SM_A_HI + rt * 400 + q * 64;
        char* al = smem + SM_A_LO + rt * 400 + q * 64;
        #pragma unroll
        for (int i = 0; i < 4; ++i) {            // 2 float4 per iter
            float4 v0 = src[2 * i];
            float4 v1 = src[2 * i + 1];
            uint4 h = make_uint4(prmt_hi(v0.x, v0.y), prmt_hi(v0.z, v0.w),
                                 prmt_hi(v1.x, v1.y), prmt_hi(v1.z, v1.w));
            uint4 l = make_uint4(
                pack_bf16(v0.x - trunc_bf16(v0.x), v0.y - trunc_bf16(v0.y)),
                pack_bf16(v0.z - trunc_bf16(v0.z), v0.w - trunc_bf16(v0.w)),
                pack_bf16(v1.x - trunc_bf16(v1.x), v1.y - trunc_bf16(v1.y)),
                pack_bf16(v1.z - trunc_bf16(v1.z), v1.w - trunc_bf16(v1.w)));
            *(uint4*)(ah + i * 16) = h;
            *(uint4*)(al + i * 16) = l;
        }

        // t2v: 16 values kk = q*16 .. q*16+15  (k = 128+kk)
        float xa = time_feat[row * F_DIM + 2 * q];
        float xb = time_feat[row * F_DIM + 2 * q + 1];
        float v[16];
        #pragma unroll
        for (int i = 0; i < 16; ++i) {
            int kk = q * 16 + i;
            float x = (i < 8) ? xa : xb;
            float a = fmaf(x, t2v_w[kk], t2v_b[kk]);
            v[i] = (kk & 7) ? __sinf(a) : a;
        }
        char* th = smem + SM_A_HI + rt * 400 + 256 + q * 32;
        char* tl = smem + SM_A_LO + rt * 400 + 256 + q * 32;
        #pragma unroll
        for (int h = 0; h < 2; ++h) {
            uint4 hp = make_uint4(prmt_hi(v[8*h+0], v[8*h+1]), prmt_hi(v[8*h+2], v[8*h+3]),
                                  prmt_hi(v[8*h+4], v[8*h+5]), prmt_hi(v[8*h+6], v[8*h+7]));
            uint4 lp = make_uint4(
                pack_bf16(v[8*h+0]-trunc_bf16(v[8*h+0]), v[8*h+1]-trunc_bf16(v[8*h+1])),
                pack_bf16(v[8*h+2]-trunc_bf16(v[8*h+2]), v[8*h+3]-trunc_bf16(v[8*h+3])),
                pack_bf16(v[8*h+4]-trunc_bf16(v[8*h+4]), v[8*h+5]-trunc_bf16(v[8*h+5])),
                pack_bf16(v[8*h+6]-trunc_bf16(v[8*h+6]), v[8*h+7]-trunc_bf16(v[8*h+7])));
            *(uint4*)(th + h * 16) = hp;
            *(uint4*)(tl + h * 16) = lp;
        }
    }
    __syncthreads();

    // --- Phase 2: mma.sync, 3-pass split bf16 ---
    const int mt = warp >> 1;
    const int nh = warp & 1;

    // ldmatrix lane addresses
    // A: lanes 0-15 rows, lanes 16-31 same rows +16B (k 8..15)
    uint32_t aAddr = sb + SM_A_HI + (mt * 16 + (lane & 15)) * 400 + (lane >> 4) * 16;
    // B: n = nh*32 + (lane&7) + ((lane>>4)<<3), +16B for lanes 8-15/24-31
    uint32_t nb = nh * 32 + (lane & 7) + ((lane >> 4) << 3);
    uint32_t bAddr = sb + SM_W_HI + nb * 400 + ((lane >> 3) & 1) * 16;

    float D[4][4];
    #pragma unroll
    for (int nt = 0; nt < 4; ++nt)
        #pragma unroll
        for (int i = 0; i < 4; ++i) D[nt][i] = 0.f;

    #pragma unroll
    for (int ks = 0; ks < NKS; ++ks) {
        uint32_t kb = ks * 32;
        uint32_t Ahi[4], Alo[4], Bhi[8], Blo[8];
        ldsm_x4(aAddr + kb,          Ahi);
        ldsm_x4(aAddr + 25600 + kb,  Alo);
        ldsm_x4(bAddr + kb,          Bhi);          // nt 0,1
        ldsm_x4(bAddr + 6400 + kb,   Bhi + 4);      // nt 2,3 (16 n-rows * 400B)
        ldsm_x4(bAddr + 25600 + kb,  Blo);
        ldsm_x4(bAddr + 32000 + kb,  Blo + 4);
        #pragma unroll
        for (int nt = 0; nt < 4; ++nt) {
            mma_bf16(D[nt], Ahi, Bhi[2 * nt], Bhi[2 * nt + 1]);
            mma_bf16(D[nt], Ahi, Blo[2 * nt], Blo[2 * nt + 1]);
            mma_bf16(D[nt], Alo, Bhi[2 * nt], Bhi[2 * nt + 1]);
        }
    }
    __syncthreads();     // all ldmatrix reads of A done before Dt overwrites it

    // --- Dt transpose: D frags -> Dt[64][72] f32 ---
    {
        float* Dt = (float*)(smem + SM_DT);
        int r0 = mt * 16 + (lane >> 2);
        int c0 = nh * 32 + (lane & 3) * 2;
        #pragma unroll
        for (int nt = 0; nt < 4; ++nt) {
            int c = c0 + nt * 8;
            *(float2*)(Dt + r0 * DT_STRIDE + c)       = make_float2(D[nt][0], D[nt][1]);
            *(float2*)(Dt + (r0 + 8) * DT_STRIDE + c) = make_float2(D[nt][2], D[nt][3]);
        }
    }
    __syncthreads();

    // --- Epilogue (R8 form): thread t = (rgrp = t>>4, jq = t&15) ---
    {
        const float* Dt = (const float*)(smem + SM_DT);
        int jq   = tid & 15;
        int rgrp = tid >> 4;
        #pragma unroll
        for (int rr = 0; rr < 4; ++rr) {
            int rl  = rgrp * 4 + rr;
            int row = ctabase + rl;
            float4 acc = *(const float4*)(Dt + rl * DT_STRIDE + 4 * jq);

            float c  = counts_s[rl];
            float pp = population[row];
            int bt = bt_ids[row], et = et_ids[row], eq = eq_ids[row];

            float4 tb = *(const float4*)(g_btype_proj + bt * D_OUT + 4 * jq);
            float4 te = *(const float4*)(g_etype_proj + et * D_OUT + 4 * jq);
            float4 tq = *(const float4*)(g_equip_proj + eq * D_OUT + 4 * jq);
            float4 v0 = *(const float4*)(g_pv0 + 4 * jq);
            float4 v1 = *(const float4*)(g_pv1 + 4 * jq);

            acc.x += c * tb.x + te.x + tq.x + pp * v0.x + v1.x;
            acc.y += c * tb.y + te.y + tq.y + pp * v0.y + v1.y;
            acc.z += c * tb.z + te.z + tq.z + pp * v0.z + v1.z;
            acc.w += c * tb.w + te.w + tq.w + pp * v0.w + v1.w;

            *(float4*)(out + (size_t)row * D_OUT + 4 * jq) = acc;
        }
    }
}

// ---------------------------------------------------------------------------
extern "C" void kernel_launch(void* const* d_in, const int* in_sizes, int n_in,
                              void* d_out, int out_size) {
    const int*   nbr     = (const int*)  d_in[0];
    const float* tfeat   = (const float*)d_in[1];
    const int*   bt      = (const int*)  d_in[2];
    const float* counts  = (const float*)d_in[3];
    const float* pop     = (const float*)d_in[4];
    const int*   et      = (const int*)  d_in[5];
    const int*   eq      = (const int*)  d_in[6];
    const float* n2v     = (const float*)d_in[7];
    const float* t2vw    = (const float*)d_in[8];
    const float* t2vb    = (const float*)d_in[9];
    const float* btt     = (const float*)d_in[10];
    const float* popw    = (const float*)d_in[11];
    const float* popb    = (const float*)d_in[12];
    const float* ett     = (const float*)d_in[13];
    const float* eqt     = (const float*)d_in[14];
    const float* pw      = (const float*)d_in[15];
    const float* pb      = (const float*)d_in[16];
    float*       out     = (float*)d_out;

    precompute_tables<<<N_BT + N_ET + N_EQ + 1 + 64, 64>>>(
        btt, ett, eqt, popw, popb, pw, pb);

    cudaFuncSetAttribute(combined_embedding_kernel,
                         cudaFuncAttributeMaxDynamicSharedMemorySize, SMEM_BYTES);
    combined_embedding_kernel<<<ROWS / TILE_M, THREADS, SMEM_BYTES>>>(
        nbr, tfeat, bt, counts, pop, et, eq, n2v, t2vw, t2vb, out);
}